// round 12
// baseline (speedup 1.0000x reference)
#include <cuda_runtime.h>
#include <mma.h>
#include <math.h>

using namespace nvcuda;

// Problem constants
#define NN   50000
#define EE   800000
#define DIN  256
#define HH1  512
#define HH2  256
#define NC   5
#define NEG_SLOPE 0.2f

// ---------------------------------------------------------------------------
// Scratch (device globals; no allocation allowed). Resolved DEVICE-SIDE only.
// ---------------------------------------------------------------------------
__device__ float g_hcat1[(size_t)NN * 1024];  // [ x@W1 | x@A1+b1 ]   ld=1024
__device__ float g_h1   [(size_t)NN * HH1];   // relu(conv1 + lin1)
__device__ float g_hcat2[(size_t)NN * 512];   // [ h@W2 | h@A2+b2 ]   ld=512
__device__ float g_h2   [(size_t)NN * HH2];   // conv2 + lin2
__device__ float g_mlp0 [(size_t)NN * HH2];
__device__ float g_mlp1 [(size_t)NN * HH2];

__device__ float g_as[NN], g_ad[NN];
__device__ float g_m[NN], g_s[NN];
__device__ float g_w[EE];

__device__ int g_src[EE];
__device__ int g_dst[EE];
__device__ int g_is64;

__device__ int g_deg[NN];
__device__ int g_rowoff[NN + 1];
__device__ int g_fill[NN];
__device__ int g_csrc[EE];
__device__ int g_ceid[EE];

// Buffer ids
#define BUF_HCAT1 1
#define BUF_H1    2
#define BUF_HCAT2 3
#define BUF_H2    4
#define BUF_MLP0  5
#define BUF_MLP1  6

__device__ __forceinline__ float* scratch(int id)
{
    switch (id) {
        case BUF_HCAT1: return g_hcat1;
        case BUF_H1:    return g_h1;
        case BUF_HCAT2: return g_hcat2;
        case BUF_H2:    return g_h2;
        case BUF_MLP0:  return g_mlp0;
        case BUF_MLP1:  return g_mlp1;
        default:        return nullptr;
    }
}

// ---------------------------------------------------------------------------
// tf32 helpers: round-to-nearest (tf32 mantissa) and hi/lo split so that
// hi + lo == x to fp32 precision, both tf32-representable.
// ---------------------------------------------------------------------------
__device__ __forceinline__ float to_tf32(float x)
{
    unsigned u;
    asm("cvt.rna.tf32.f32 %0, %1;" : "=r"(u) : "f"(x));
    return __uint_as_float(u);
}

__device__ __forceinline__ void split_tf32(float x, float& hi, float& lo)
{
    hi = to_tf32(x);
    lo = to_tf32(x - hi);
}

// ---------------------------------------------------------------------------
// Edge-index dtype detection + conversion.
// ---------------------------------------------------------------------------
__global__ void detect_dtype_kernel(const int* __restrict__ raw)
{
    int all_zero = 1;
    for (int k = 0; k < 64; k++)
        if (raw[2 * k + 1] != 0) { all_zero = 0; break; }
    g_is64 = all_zero;
}

__global__ void convert_edges_kernel(const int* __restrict__ raw)
{
    int e = blockIdx.x * blockDim.x + threadIdx.x;
    if (e >= EE) return;
    if (g_is64) {
        g_src[e] = raw[2 * e];
        g_dst[e] = raw[2 * (EE + e)];
    } else {
        g_src[e] = raw[e];
        g_dst[e] = raw[EE + e];
    }
}

// ---------------------------------------------------------------------------
// Tensor-core GEMM (3xTF32): C[M,N] = A[M,K] @ B[K,N] (+bias) (+relu).
// BM=BN=128, BK=16. 256 threads = 8 warps in a 2x4 grid; warp tile 64x32 =
// 4x2 wmma m16n16k8 tiles. Inputs split hi/lo at staging; 3 mma passes per
// tile (hi*hi, hi*lo, lo*hi) accumulate into one fp32 fragment set.
// Epilogue stages C through shared memory (two 64-col halves) for fused
// bias + relu + vectorized stores.
// ---------------------------------------------------------------------------
template <bool RELU, bool BIAS>
__global__ __launch_bounds__(256) void tgemm_kernel(
    const float* __restrict__ Aext, int Aid,
    const float* __restrict__ B, const float* __restrict__ bias,
    int Cid, int coff,
    int M, int N, int K, int ldc)
{
    const float* A = Aext ? Aext : scratch(Aid);
    float* C = scratch(Cid) + coff;

    __shared__ union {
        struct {
            float Ahi[128][20];   // padded ld=20
            float Alo[128][20];
            float Bhi[16][132];   // padded ld=132
            float Blo[16][132];
        } mm;
        float Cst[128][68];       // epilogue staging (64 cols + pad)
    } sm;

    int tid = threadIdx.x;
    int warp = tid >> 5;
    int wr = warp >> 2;          // 0..1  -> warp row (64 rows each)
    int wc = warp & 3;           // 0..3  -> warp col (32 cols each)
    int row0 = blockIdx.y * 128;
    int col0 = blockIdx.x * 128;

    wmma::fragment<wmma::accumulator, 16, 16, 8, float> acc[4][2];
#pragma unroll
    for (int mt = 0; mt < 4; mt++)
#pragma unroll
        for (int nt = 0; nt < 2; nt++) wmma::fill_fragment(acc[mt][nt], 0.f);

    for (int k0 = 0; k0 < K; k0 += 16) {
        // Stage A tile (128 x 16) with hi/lo split: 512 float4, 2 per thread
#pragma unroll
        for (int i = 0; i < 2; i++) {
            int idx = tid + i * 256;
            int r = idx >> 2;        // 0..127
            int c4 = (idx & 3) * 4;  // 0,4,8,12
            float4 v = make_float4(0.f, 0.f, 0.f, 0.f);
            if (row0 + r < M)
                v = *(const float4*)(A + (size_t)(row0 + r) * K + k0 + c4);
            float e[4] = {v.x, v.y, v.z, v.w};
#pragma unroll
            for (int j = 0; j < 4; j++) {
                float hi, lo;
                split_tf32(e[j], hi, lo);
                sm.mm.Ahi[r][c4 + j] = hi;
                sm.mm.Alo[r][c4 + j] = lo;
            }
        }
        // Stage B tile (16 x 128) with hi/lo split
#pragma unroll
        for (int i = 0; i < 2; i++) {
            int idx = tid + i * 256;
            int r = idx >> 5;        // 0..15
            int c4 = (idx & 31) * 4; // 0..124
            float4 v = *(const float4*)(B + (size_t)(k0 + r) * N + col0 + c4);
            float e[4] = {v.x, v.y, v.z, v.w};
#pragma unroll
            for (int j = 0; j < 4; j++) {
                float hi, lo;
                split_tf32(e[j], hi, lo);
                sm.mm.Bhi[r][c4 + j] = hi;
                sm.mm.Blo[r][c4 + j] = lo;
            }
        }
        __syncthreads();

#pragma unroll
        for (int kk = 0; kk < 16; kk += 8) {
            wmma::fragment<wmma::matrix_b, 16, 16, 8, wmma::precision::tf32, wmma::row_major> bhi[2], blo[2];
#pragma unroll
            for (int nt = 0; nt < 2; nt++) {
                int c = wc * 32 + nt * 16;
                wmma::load_matrix_sync(bhi[nt], &sm.mm.Bhi[kk][c], 132);
                wmma::load_matrix_sync(blo[nt], &sm.mm.Blo[kk][c], 132);
            }
#pragma unroll
            for (int mt = 0; mt < 4; mt++) {
                int r = wr * 64 + mt * 16;
                wmma::fragment<wmma::matrix_a, 16, 16, 8, wmma::precision::tf32, wmma::row_major> ahi, alo;
                wmma::load_matrix_sync(ahi, &sm.mm.Ahi[r][kk], 20);
                wmma::load_matrix_sync(alo, &sm.mm.Alo[r][kk], 20);
#pragma unroll
                for (int nt = 0; nt < 2; nt++) {
                    wmma::mma_sync(acc[mt][nt], ahi, bhi[nt], acc[mt][nt]);
                    wmma::mma_sync(acc[mt][nt], ahi, blo[nt], acc[mt][nt]);
                    wmma::mma_sync(acc[mt][nt], alo, bhi[nt], acc[mt][nt]);
                }
            }
        }
        __syncthreads();
    }

    // Epilogue: two 64-column halves through shared staging
#pragma unroll
    for (int half = 0; half < 2; half++) {
        if ((wc >> 1) == half) {
            int wcl = wc & 1;   // 0..1 within the half
#pragma unroll
            for (int mt = 0; mt < 4; mt++)
#pragma unroll
                for (int nt = 0; nt < 2; nt++)
                    wmma::store_matrix_sync(&sm.Cst[wr * 64 + mt * 16][wcl * 32 + nt * 16],
                                            acc[mt][nt], 68, wmma::mem_row_major);
        }
        __syncthreads();
        // 128 rows x 64 cols = 2048 float4; 8 per thread
#pragma unroll
        for (int i = 0; i < 8; i++) {
            int idx = tid + i * 256;
            int r = idx >> 4;            // 0..127
            int c = (idx & 15) * 4;      // 0..60
            if (row0 + r < M) {
                int gc = col0 + half * 64 + c;
                float4 v = *(const float4*)(&sm.Cst[r][c]);
                if (BIAS) {
                    v.x += bias[gc];
                    v.y += bias[gc + 1];
                    v.z += bias[gc + 2];
                    v.w += bias[gc + 3];
                }
                if (RELU) {
                    v.x = fmaxf(v.x, 0.f);
                    v.y = fmaxf(v.y, 0.f);
                    v.z = fmaxf(v.z, 0.f);
                    v.w = fmaxf(v.w, 0.f);
                }
                *(float4*)(C + (size_t)(row0 + r) * ldc + gc) = v;
            }
        }
        __syncthreads();
    }
}

// ---------------------------------------------------------------------------
// Attention dot products: warp per node.
// ---------------------------------------------------------------------------
__global__ void att_dots_kernel(int hid, int C, int ld,
                                const float* __restrict__ asv,
                                const float* __restrict__ adv)
{
    const float* h = scratch(hid);
    int warp = (blockIdx.x * blockDim.x + threadIdx.x) >> 5;
    int lane = threadIdx.x & 31;
    if (warp >= NN) return;
    const float* row = h + (size_t)warp * ld;
    float s1 = 0.f, s2 = 0.f;
    for (int c = lane; c < C; c += 32) {
        float v = row[c];
        s1 += v * asv[c];
        s2 += v * adv[c];
    }
#pragma unroll
    for (int o = 16; o; o >>= 1) {
        s1 += __shfl_xor_sync(0xffffffffu, s1, o);
        s2 += __shfl_xor_sync(0xffffffffu, s2, o);
    }
    if (lane == 0) { g_as[warp] = s1; g_ad[warp] = s2; }
}

// ---------------------------------------------------------------------------
// CSR build
// ---------------------------------------------------------------------------
__global__ void init_csr_kernel()
{
    int i = blockIdx.x * blockDim.x + threadIdx.x;
    if (i < NN) { g_deg[i] = 0; g_fill[i] = 0; }
}

__global__ void init_ms_kernel()
{
    int i = blockIdx.x * blockDim.x + threadIdx.x;
    if (i < NN) { g_m[i] = -1e30f; g_s[i] = 0.f; }
}

__global__ void hist_kernel()
{
    int e = blockIdx.x * blockDim.x + threadIdx.x;
    if (e < EE) atomicAdd(&g_deg[g_dst[e]], 1);
}

// Single-block exclusive scan of g_deg -> g_rowoff (NN+1 entries)
__global__ __launch_bounds__(1024) void scan_kernel()
{
    __shared__ int wsum[32];
    __shared__ int running;
    int tid = threadIdx.x;
    int lane = tid & 31, wid = tid >> 5;
    if (tid == 0) running = 0;
    __syncthreads();
    for (int base = 0; base < NN; base += 1024) {
        int i = base + tid;
        int v = (i < NN) ? g_deg[i] : 0;
        int x = v;
#pragma unroll
        for (int o = 1; o < 32; o <<= 1) {
            int y = __shfl_up_sync(0xffffffffu, x, o);
            if (lane >= o) x += y;
        }
        if (lane == 31) wsum[wid] = x;
        __syncthreads();
        if (wid == 0) {
            int w = wsum[lane];
#pragma unroll
            for (int o = 1; o < 32; o <<= 1) {
                int y = __shfl_up_sync(0xffffffffu, w, o);
                if (lane >= o) w += y;
            }
            wsum[lane] = w;
        }
        __syncthreads();
        int excl = x - v + (wid > 0 ? wsum[wid - 1] : 0);
        if (i < NN) g_rowoff[i] = running + excl;
        int total = wsum[31];
        __syncthreads();
        if (tid == 0) running += total;
        __syncthreads();
    }
    if (tid == 0) g_rowoff[NN] = running;
}

__global__ void fill_kernel()
{
    int e = blockIdx.x * blockDim.x + threadIdx.x;
    if (e < EE) {
        int d = g_dst[e];
        int p = g_rowoff[d] + atomicAdd(&g_fill[d], 1);
        g_csrc[p] = g_src[e];
        g_ceid[p] = e;
    }
}

// ---------------------------------------------------------------------------
// Edge softmax
// ---------------------------------------------------------------------------
__device__ __forceinline__ void atomicMaxF(float* addr, float val)
{
    int old = __float_as_int(*addr);
    while (__int_as_float(old) < val) {
        int assumed = old;
        old = atomicCAS((int*)addr, assumed, __float_as_int(val));
        if (old == assumed) break;
    }
}

__global__ void edge_max_kernel()
{
    int e = blockIdx.x * blockDim.x + threadIdx.x;
    if (e >= EE) return;
    float t = g_as[g_src[e]] + g_ad[g_dst[e]];
    t = (t > 0.f) ? t : NEG_SLOPE * t;   // leaky relu
    g_w[e] = t;
    atomicMaxF(&g_m[g_dst[e]], t);
}

__global__ void edge_exp_kernel()
{
    int e = blockIdx.x * blockDim.x + threadIdx.x;
    if (e >= EE) return;
    int d = g_dst[e];
    float w = expf(g_w[e] - g_m[d]);
    g_w[e] = w;
    atomicAdd(&g_s[d], w);
}

// ---------------------------------------------------------------------------
// Aggregation: block per dst node, C/4 threads, one float4 per thread.
// ---------------------------------------------------------------------------
template <int C, bool RELU>
__global__ void aggregate_kernel(int hid, int hoff, int roff, int ldh,
                                 const float* __restrict__ bias, int oid)
{
    const float* base = scratch(hid);
    const float* h = base + hoff;
    const float* res = base + roff;
    float* out = scratch(oid);

    int n = blockIdx.x;
    int t4 = threadIdx.x * 4;           // column offset
    int beg = g_rowoff[n], end = g_rowoff[n + 1];
    float inv = 1.0f / (g_s[n] + 1e-16f);
    float4 acc = make_float4(0.f, 0.f, 0.f, 0.f);
    int j = beg;
    for (; j + 1 < end; j += 2) {
        int s0 = g_csrc[j], s1 = g_csrc[j + 1];
        float c0 = g_w[g_ceid[j]] * inv;
        float c1 = g_w[g_ceid[j + 1]] * inv;
        float4 h0 = *(const float4*)(h + (size_t)s0 * ldh + t4);
        float4 h1 = *(const float4*)(h + (size_t)s1 * ldh + t4);
        acc.x += c0 * h0.x + c1 * h1.x;
        acc.y += c0 * h0.y + c1 * h1.y;
        acc.z += c0 * h0.z + c1 * h1.z;
        acc.w += c0 * h0.w + c1 * h1.w;
    }
    if (j < end) {
        int s0 = g_csrc[j];
        float c0 = g_w[g_ceid[j]] * inv;
        float4 h0 = *(const float4*)(h + (size_t)s0 * ldh + t4);
        acc.x += c0 * h0.x;
        acc.y += c0 * h0.y;
        acc.z += c0 * h0.z;
        acc.w += c0 * h0.w;
    }
    float4 r = *(const float4*)(res + (size_t)n * ldh + t4);
    float4 o;
    o.x = acc.x + r.x + bias[t4 + 0];
    o.y = acc.y + r.y + bias[t4 + 1];
    o.z = acc.z + r.z + bias[t4 + 2];
    o.w = acc.w + r.w + bias[t4 + 3];
    if (RELU) {
        o.x = fmaxf(o.x, 0.f);
        o.y = fmaxf(o.y, 0.f);
        o.z = fmaxf(o.z, 0.f);
        o.w = fmaxf(o.w, 0.f);
    }
    *(float4*)(out + (size_t)n * C + t4) = o;
}

// ---------------------------------------------------------------------------
// Classifier + softmax: warp per node.
// ---------------------------------------------------------------------------
__global__ void fc_softmax_kernel(int hid,
                                  const float* __restrict__ fcw,
                                  const float* __restrict__ fcb,
                                  float* __restrict__ out)
{
    const float* h = scratch(hid);
    int warp = (blockIdx.x * blockDim.x + threadIdx.x) >> 5;
    int lane = threadIdx.x & 31;
    if (warp >= NN) return;
    const float* row = h + (size_t)warp * HH2;
    float acc[NC] = {0.f, 0.f, 0.f, 0.f, 0.f};
    for (int c = lane; c < HH2; c += 32) {
        float v = row[c];
#pragma unroll
        for (int j = 0; j < NC; j++) acc[j] += v * fcw[c * NC + j];
    }
#pragma unroll
    for (int j = 0; j < NC; j++)
#pragma unroll
        for (int o = 16; o; o >>= 1)
            acc[j] += __shfl_xor_sync(0xffffffffu, acc[j], o);
    if (lane == 0) {
        float mx = -1e30f;
#pragma unroll
        for (int j = 0; j < NC; j++) {
            acc[j] += fcb[j];
            mx = fmaxf(mx, acc[j]);
        }
        float s = 0.f;
#pragma unroll
        for (int j = 0; j < NC; j++) {
            acc[j] = expf(acc[j] - mx);
            s += acc[j];
        }
        float invs = 1.0f / s;
#pragma unroll
        for (int j = 0; j < NC; j++) out[(size_t)warp * NC + j] = acc[j] * invs;
    }
}

// ---------------------------------------------------------------------------
// Launch
// ---------------------------------------------------------------------------
static inline void run_gemm(const float* Aext, int Aid,
                            const float* B, const float* bias,
                            int Cid, int coff,
                            int M, int N, int K, int ldc,
                            bool relu, cudaStream_t st)
{
    dim3 grid(N / 128, (M + 127) / 128);
    if (relu) {
        if (bias) tgemm_kernel<true, true><<<grid, 256, 0, st>>>(Aext, Aid, B, bias, Cid, coff, M, N, K, ldc);
        else      tgemm_kernel<true, false><<<grid, 256, 0, st>>>(Aext, Aid, B, bias, Cid, coff, M, N, K, ldc);
    } else {
        if (bias) tgemm_kernel<false, true><<<grid, 256, 0, st>>>(Aext, Aid, B, bias, Cid, coff, M, N, K, ldc);
        else      tgemm_kernel<false, false><<<grid, 256, 0, st>>>(Aext, Aid, B, bias, Cid, coff, M, N, K, ldc);
    }
}

extern "C" void kernel_launch(void* const* d_in, const int* in_sizes, int n_in,
                              void* d_out, int out_size)
{
    const float* x        = (const float*)d_in[0];
    const int*   ei_raw   = (const int*)d_in[1];   // int32 or int64 — detected on device
    const float* W1       = (const float*)d_in[2];
    const float* att_src1 = (const float*)d_in[3];
    const float* att_dst1 = (const float*)d_in[4];
    const float* b_conv1  = (const float*)d_in[5];
    const float* A1       = (const float*)d_in[6];
    const float* b1       = (const float*)d_in[7];
    const float* W2       = (const float*)d_in[8];
    const float* att_src2 = (const float*)d_in[9];
    const float* att_dst2 = (const float*)d_in[10];
    const float* b_conv2  = (const float*)d_in[11];
    const float* A2       = (const float*)d_in[12];
    const float* b2       = (const float*)d_in[13];
    const float* Hw1      = (const float*)d_in[14];
    const float* Hb1      = (const float*)d_in[15];
    const float* Hw2      = (const float*)d_in[16];
    const float* Hb2      = (const float*)d_in[17];
    const float* Hw3      = (const float*)d_in[18];
    const float* Hb3      = (const float*)d_in[19];
    const float* fcw      = (const float*)d_in[20];
    const float* fcb      = (const float*)d_in[21];
    float*       out      = (float*)d_out;

    cudaStream_t st = 0;  // default stream (captured by harness)

    const int NB = (NN + 255) / 256;
    const int EB = (EE + 255) / 256;
    const int WB = (NN * 32 + 255) / 256;  // warp-per-node kernels

    // ---- Edge decode (dtype-agnostic) + CSR build (once per launch) ----
    detect_dtype_kernel<<<1, 1, 0, st>>>(ei_raw);
    convert_edges_kernel<<<EB, 256, 0, st>>>(ei_raw);
    init_csr_kernel<<<NB, 256, 0, st>>>();
    hist_kernel<<<EB, 256, 0, st>>>();
    scan_kernel<<<1, 1024, 0, st>>>();
    fill_kernel<<<EB, 256, 0, st>>>();

    // ---- Layer 1: hcat1 = [x@W1 | x@A1+b1] ----
    run_gemm(x, 0, W1, nullptr, BUF_HCAT1, 0,   NN, HH1, DIN, 1024, false, st);
    run_gemm(x, 0, A1, b1,      BUF_HCAT1, HH1, NN, HH1, DIN, 1024, false, st);
    att_dots_kernel<<<WB, 256, 0, st>>>(BUF_HCAT1, HH1, 1024, att_src1, att_dst1);
    init_ms_kernel<<<NB, 256, 0, st>>>();
    edge_max_kernel<<<EB, 256, 0, st>>>();
    edge_exp_kernel<<<EB, 256, 0, st>>>();
    aggregate_kernel<HH1, true><<<NN, HH1 / 4, 0, st>>>(
        BUF_HCAT1, 0, HH1, 1024, b_conv1, BUF_H1);

    // ---- Layer 2: hcat2 = [h1@W2 | h1@A2+b2] ----
    run_gemm(nullptr, BUF_H1, W2, nullptr, BUF_HCAT2, 0,   NN, HH2, HH1, 512, false, st);
    run_gemm(nullptr, BUF_H1, A2, b2,      BUF_HCAT2, HH2, NN, HH2, HH1, 512, false, st);
    att_dots_kernel<<<WB, 256, 0, st>>>(BUF_HCAT2, HH2, 512, att_src2, att_dst2);
    init_ms_kernel<<<NB, 256, 0, st>>>();
    edge_max_kernel<<<EB, 256, 0, st>>>();
    edge_exp_kernel<<<EB, 256, 0, st>>>();
    aggregate_kernel<HH2, false><<<NN, HH2 / 4, 0, st>>>(
        BUF_HCAT2, 0, HH2, 512, b_conv2, BUF_H2);

    // ---- MLP ----
    run_gemm(nullptr, BUF_H2,   Hw1, Hb1, BUF_MLP0, 0, NN, HH2, HH2, HH2, true, st);
    run_gemm(nullptr, BUF_MLP0, Hw2, Hb2, BUF_MLP1, 0, NN, HH2, HH2, HH2, true, st);
    run_gemm(nullptr, BUF_MLP1, Hw3, Hb3, BUF_MLP0, 0, NN, HH2, HH2, HH2, true, st);

    // ---- Classifier + softmax ----
    fc_softmax_kernel<<<WB, 256, 0, st>>>(BUF_MLP0, fcw, fcb, out);
}

// round 14
// speedup vs baseline: 2.1270x; 2.1270x over previous
#include <cuda_runtime.h>
#include <cuda_bf16.h>
#include <mma.h>
#include <math.h>

using namespace nvcuda;

// Problem constants
#define NN   50000
#define EE   800000
#define DIN  256
#define HH1  512
#define HH2  256
#define NC   5
#define NEG_SLOPE 0.2f

// ---------------------------------------------------------------------------
// Scratch (device globals; no allocation allowed). Resolved DEVICE-SIDE only.
// ---------------------------------------------------------------------------
__device__ float g_hcat1[(size_t)NN * 1024];  // [ x@W1 | x@A1+b1 ]   ld=1024
__device__ float g_h1   [(size_t)NN * HH1];   // relu(conv1 + lin1)
__device__ float g_hcat2[(size_t)NN * 512];   // [ h@W2 | h@A2+b2 ]   ld=512
__device__ float g_h2   [(size_t)NN * HH2];   // conv2 + lin2
__device__ float g_mlp0 [(size_t)NN * HH2];
__device__ float g_mlp1 [(size_t)NN * HH2];

__device__ float g_as[NN], g_ad[NN];
__device__ float g_m[NN], g_s[NN];
__device__ float g_w[EE];

__device__ int g_src[EE];
__device__ int g_dst[EE];
__device__ int g_is64;

__device__ int g_deg[NN];
__device__ int g_rowoff[NN + 1];
__device__ int g_fill[NN];
__device__ int g_csrc[EE];
__device__ int g_ceid[EE];

// Buffer ids
#define BUF_HCAT1 1
#define BUF_H1    2
#define BUF_HCAT2 3
#define BUF_H2    4
#define BUF_MLP0  5
#define BUF_MLP1  6

__device__ __forceinline__ float* scratch(int id)
{
    switch (id) {
        case BUF_HCAT1: return g_hcat1;
        case BUF_H1:    return g_h1;
        case BUF_HCAT2: return g_hcat2;
        case BUF_H2:    return g_h2;
        case BUF_MLP0:  return g_mlp0;
        case BUF_MLP1:  return g_mlp1;
        default:        return nullptr;
    }
}

// bf16 hi/lo split: hi = bf16(x), lo = bf16(x - hi). hi+lo carries ~16
// mantissa bits of x.
__device__ __forceinline__ void split_bf16(float x, __nv_bfloat16& hi, __nv_bfloat16& lo)
{
    hi = __float2bfloat16(x);
    lo = __float2bfloat16(x - __bfloat162float(hi));
}

// ---------------------------------------------------------------------------
// Edge-index dtype detection + conversion.
// ---------------------------------------------------------------------------
__global__ void detect_dtype_kernel(const int* __restrict__ raw)
{
    int all_zero = 1;
    for (int k = 0; k < 64; k++)
        if (raw[2 * k + 1] != 0) { all_zero = 0; break; }
    g_is64 = all_zero;
}

__global__ void convert_edges_kernel(const int* __restrict__ raw)
{
    int e = blockIdx.x * blockDim.x + threadIdx.x;
    if (e >= EE) return;
    if (g_is64) {
        g_src[e] = raw[2 * e];
        g_dst[e] = raw[2 * (EE + e)];
    } else {
        g_src[e] = raw[e];
        g_dst[e] = raw[EE + e];
    }
}

// ---------------------------------------------------------------------------
// Tensor-core GEMM (3x bf16 split): C[M,N] = A[M,K] @ B[K,N] (+bias)(+relu).
// BM=BN=128, BK=32. 256 threads = 8 warps (2x4); warp tile 64x32 = 4x2 wmma
// m16n16k16 tiles. Inputs split hi/lo bf16 at staging; 3 mma passes per tile
// (hi*hi, hi*lo, lo*hi) accumulate into fp32 fragments.
// Epilogue stages C through shared memory for fused bias+relu float4 stores.
// ---------------------------------------------------------------------------
template <bool RELU, bool BIAS>
__global__ __launch_bounds__(256) void tgemm_kernel(
    const float* __restrict__ Aext, int Aid,
    const float* __restrict__ B, const float* __restrict__ bias,
    int Cid, int coff,
    int M, int N, int K, int ldc)
{
    const float* A = Aext ? Aext : scratch(Aid);
    float* C = scratch(Cid) + coff;

    __shared__ union {
        struct {
            __nv_bfloat16 Ahi[128][40];   // padded ld=40 (80B, 16B-multiple)
            __nv_bfloat16 Alo[128][40];
            __nv_bfloat16 Bhi[32][136];   // padded ld=136 (272B)
            __nv_bfloat16 Blo[32][136];
        } mm;
        float Cst[128][68];               // epilogue staging (64 cols + pad)
    } sm;

    int tid = threadIdx.x;
    int warp = tid >> 5;
    int wr = warp >> 2;          // 0..1  -> warp row (64 rows each)
    int wc = warp & 3;           // 0..3  -> warp col (32 cols each)
    int row0 = blockIdx.y * 128;
    int col0 = blockIdx.x * 128;

    wmma::fragment<wmma::accumulator, 16, 16, 16, float> acc[4][2];
#pragma unroll
    for (int mt = 0; mt < 4; mt++)
#pragma unroll
        for (int nt = 0; nt < 2; nt++) wmma::fill_fragment(acc[mt][nt], 0.f);

    for (int k0 = 0; k0 < K; k0 += 32) {
        // Stage A tile (128 x 32): 1024 float4, 4 per thread, hi/lo split
#pragma unroll
        for (int i = 0; i < 4; i++) {
            int idx = tid + i * 256;
            int r = idx >> 3;        // 0..127
            int c4 = (idx & 7) * 4;  // 0..28
            float4 v = make_float4(0.f, 0.f, 0.f, 0.f);
            if (row0 + r < M)
                v = *(const float4*)(A + (size_t)(row0 + r) * K + k0 + c4);
            float e[4] = {v.x, v.y, v.z, v.w};
#pragma unroll
            for (int j = 0; j < 4; j++) {
                __nv_bfloat16 hi, lo;
                split_bf16(e[j], hi, lo);
                sm.mm.Ahi[r][c4 + j] = hi;
                sm.mm.Alo[r][c4 + j] = lo;
            }
        }
        // Stage B tile (32 x 128): 1024 float4, 4 per thread, hi/lo split
#pragma unroll
        for (int i = 0; i < 4; i++) {
            int idx = tid + i * 256;
            int r = idx >> 5;        // 0..31
            int c4 = (idx & 31) * 4; // 0..124
            float4 v = *(const float4*)(B + (size_t)(k0 + r) * N + col0 + c4);
            float e[4] = {v.x, v.y, v.z, v.w};
#pragma unroll
            for (int j = 0; j < 4; j++) {
                __nv_bfloat16 hi, lo;
                split_bf16(e[j], hi, lo);
                sm.mm.Bhi[r][c4 + j] = hi;
                sm.mm.Blo[r][c4 + j] = lo;
            }
        }
        __syncthreads();

#pragma unroll
        for (int kk = 0; kk < 32; kk += 16) {
            wmma::fragment<wmma::matrix_b, 16, 16, 16, __nv_bfloat16, wmma::row_major> bhi[2], blo[2];
#pragma unroll
            for (int nt = 0; nt < 2; nt++) {
                int c = wc * 32 + nt * 16;
                wmma::load_matrix_sync(bhi[nt], &sm.mm.Bhi[kk][c], 136);
                wmma::load_matrix_sync(blo[nt], &sm.mm.Blo[kk][c], 136);
            }
#pragma unroll
            for (int mt = 0; mt < 4; mt++) {
                int r = wr * 64 + mt * 16;
                wmma::fragment<wmma::matrix_a, 16, 16, 16, __nv_bfloat16, wmma::row_major> ahi, alo;
                wmma::load_matrix_sync(ahi, &sm.mm.Ahi[r][kk], 40);
                wmma::load_matrix_sync(alo, &sm.mm.Alo[r][kk], 40);
#pragma unroll
                for (int nt = 0; nt < 2; nt++) {
                    wmma::mma_sync(acc[mt][nt], ahi, bhi[nt], acc[mt][nt]);
                    wmma::mma_sync(acc[mt][nt], ahi, blo[nt], acc[mt][nt]);
                    wmma::mma_sync(acc[mt][nt], alo, bhi[nt], acc[mt][nt]);
                }
            }
        }
        __syncthreads();
    }

    // Epilogue: two 64-column halves through shared staging
#pragma unroll
    for (int half = 0; half < 2; half++) {
        if ((wc >> 1) == half) {
            int wcl = wc & 1;   // 0..1 within the half
#pragma unroll
            for (int mt = 0; mt < 4; mt++)
#pragma unroll
                for (int nt = 0; nt < 2; nt++)
                    wmma::store_matrix_sync(&sm.Cst[wr * 64 + mt * 16][wcl * 32 + nt * 16],
                                            acc[mt][nt], 68, wmma::mem_row_major);
        }
        __syncthreads();
        // 128 rows x 64 cols = 2048 float4; 8 per thread
#pragma unroll
        for (int i = 0; i < 8; i++) {
            int idx = tid + i * 256;
            int r = idx >> 4;            // 0..127
            int c = (idx & 15) * 4;      // 0..60
            if (row0 + r < M) {
                int gc = col0 + half * 64 + c;
                float4 v = *(const float4*)(&sm.Cst[r][c]);
                if (BIAS) {
                    v.x += bias[gc];
                    v.y += bias[gc + 1];
                    v.z += bias[gc + 2];
                    v.w += bias[gc + 3];
                }
                if (RELU) {
                    v.x = fmaxf(v.x, 0.f);
                    v.y = fmaxf(v.y, 0.f);
                    v.z = fmaxf(v.z, 0.f);
                    v.w = fmaxf(v.w, 0.f);
                }
                *(float4*)(C + (size_t)(row0 + r) * ldc + gc) = v;
            }
        }
        __syncthreads();
    }
}

// ---------------------------------------------------------------------------
// Attention dot products: warp per node.
// ---------------------------------------------------------------------------
__global__ void att_dots_kernel(int hid, int C, int ld,
                                const float* __restrict__ asv,
                                const float* __restrict__ adv)
{
    const float* h = scratch(hid);
    int warp = (blockIdx.x * blockDim.x + threadIdx.x) >> 5;
    int lane = threadIdx.x & 31;
    if (warp >= NN) return;
    const float* row = h + (size_t)warp * ld;
    float s1 = 0.f, s2 = 0.f;
    for (int c = lane; c < C; c += 32) {
        float v = row[c];
        s1 += v * asv[c];
        s2 += v * adv[c];
    }
#pragma unroll
    for (int o = 16; o; o >>= 1) {
        s1 += __shfl_xor_sync(0xffffffffu, s1, o);
        s2 += __shfl_xor_sync(0xffffffffu, s2, o);
    }
    if (lane == 0) { g_as[warp] = s1; g_ad[warp] = s2; }
}

// ---------------------------------------------------------------------------
// CSR build
// ---------------------------------------------------------------------------
__global__ void init_csr_kernel()
{
    int i = blockIdx.x * blockDim.x + threadIdx.x;
    if (i < NN) { g_deg[i] = 0; g_fill[i] = 0; }
}

__global__ void init_ms_kernel()
{
    int i = blockIdx.x * blockDim.x + threadIdx.x;
    if (i < NN) { g_m[i] = -1e30f; g_s[i] = 0.f; }
}

__global__ void hist_kernel()
{
    int e = blockIdx.x * blockDim.x + threadIdx.x;
    if (e < EE) atomicAdd(&g_deg[g_dst[e]], 1);
}

// Single-block exclusive scan of g_deg -> g_rowoff (NN+1 entries)
__global__ __launch_bounds__(1024) void scan_kernel()
{
    __shared__ int wsum[32];
    __shared__ int running;
    int tid = threadIdx.x;
    int lane = tid & 31, wid = tid >> 5;
    if (tid == 0) running = 0;
    __syncthreads();
    for (int base = 0; base < NN; base += 1024) {
        int i = base + tid;
        int v = (i < NN) ? g_deg[i] : 0;
        int x = v;
#pragma unroll
        for (int o = 1; o < 32; o <<= 1) {
            int y = __shfl_up_sync(0xffffffffu, x, o);
            if (lane >= o) x += y;
        }
        if (lane == 31) wsum[wid] = x;
        __syncthreads();
        if (wid == 0) {
            int w = wsum[lane];
#pragma unroll
            for (int o = 1; o < 32; o <<= 1) {
                int y = __shfl_up_sync(0xffffffffu, w, o);
                if (lane >= o) w += y;
            }
            wsum[lane] = w;
        }
        __syncthreads();
        int excl = x - v + (wid > 0 ? wsum[wid - 1] : 0);
        if (i < NN) g_rowoff[i] = running + excl;
        int total = wsum[31];
        __syncthreads();
        if (tid == 0) running += total;
        __syncthreads();
    }
    if (tid == 0) g_rowoff[NN] = running;
}

__global__ void fill_kernel()
{
    int e = blockIdx.x * blockDim.x + threadIdx.x;
    if (e < EE) {
        int d = g_dst[e];
        int p = g_rowoff[d] + atomicAdd(&g_fill[d], 1);
        g_csrc[p] = g_src[e];
        g_ceid[p] = e;
    }
}

// ---------------------------------------------------------------------------
// Edge softmax
// ---------------------------------------------------------------------------
__device__ __forceinline__ void atomicMaxF(float* addr, float val)
{
    int old = __float_as_int(*addr);
    while (__int_as_float(old) < val) {
        int assumed = old;
        old = atomicCAS((int*)addr, assumed, __float_as_int(val));
        if (old == assumed) break;
    }
}

__global__ void edge_max_kernel()
{
    int e = blockIdx.x * blockDim.x + threadIdx.x;
    if (e >= EE) return;
    float t = g_as[g_src[e]] + g_ad[g_dst[e]];
    t = (t > 0.f) ? t : NEG_SLOPE * t;   // leaky relu
    g_w[e] = t;
    atomicMaxF(&g_m[g_dst[e]], t);
}

__global__ void edge_exp_kernel()
{
    int e = blockIdx.x * blockDim.x + threadIdx.x;
    if (e >= EE) return;
    int d = g_dst[e];
    float w = expf(g_w[e] - g_m[d]);
    g_w[e] = w;
    atomicAdd(&g_s[d], w);
}

// ---------------------------------------------------------------------------
// Aggregation: block per dst node, C/4 threads, one float4 per thread.
// ---------------------------------------------------------------------------
template <int C, bool RELU>
__global__ void aggregate_kernel(int hid, int hoff, int roff, int ldh,
                                 const float* __restrict__ bias, int oid)
{
    const float* base = scratch(hid);
    const float* h = base + hoff;
    const float* res = base + roff;
    float* out = scratch(oid);

    int n = blockIdx.x;
    int t4 = threadIdx.x * 4;           // column offset
    int beg = g_rowoff[n], end = g_rowoff[n + 1];
    float inv = 1.0f / (g_s[n] + 1e-16f);
    float4 acc = make_float4(0.f, 0.f, 0.f, 0.f);
    int j = beg;
    for (; j + 1 < end; j += 2) {
        int s0 = g_csrc[j], s1 = g_csrc[j + 1];
        float c0 = g_w[g_ceid[j]] * inv;
        float c1 = g_w[g_ceid[j + 1]] * inv;
        float4 h0 = *(const float4*)(h + (size_t)s0 * ldh + t4);
        float4 h1 = *(const float4*)(h + (size_t)s1 * ldh + t4);
        acc.x += c0 * h0.x + c1 * h1.x;
        acc.y += c0 * h0.y + c1 * h1.y;
        acc.z += c0 * h0.z + c1 * h1.z;
        acc.w += c0 * h0.w + c1 * h1.w;
    }
    if (j < end) {
        int s0 = g_csrc[j];
        float c0 = g_w[g_ceid[j]] * inv;
        float4 h0 = *(const float4*)(h + (size_t)s0 * ldh + t4);
        acc.x += c0 * h0.x;
        acc.y += c0 * h0.y;
        acc.z += c0 * h0.z;
        acc.w += c0 * h0.w;
    }
    float4 r = *(const float4*)(res + (size_t)n * ldh + t4);
    float4 o;
    o.x = acc.x + r.x + bias[t4 + 0];
    o.y = acc.y + r.y + bias[t4 + 1];
    o.z = acc.z + r.z + bias[t4 + 2];
    o.w = acc.w + r.w + bias[t4 + 3];
    if (RELU) {
        o.x = fmaxf(o.x, 0.f);
        o.y = fmaxf(o.y, 0.f);
        o.z = fmaxf(o.z, 0.f);
        o.w = fmaxf(o.w, 0.f);
    }
    *(float4*)(out + (size_t)n * C + t4) = o;
}

// ---------------------------------------------------------------------------
// Classifier + softmax: warp per node.
// ---------------------------------------------------------------------------
__global__ void fc_softmax_kernel(int hid,
                                  const float* __restrict__ fcw,
                                  const float* __restrict__ fcb,
                                  float* __restrict__ out)
{
    const float* h = scratch(hid);
    int warp = (blockIdx.x * blockDim.x + threadIdx.x) >> 5;
    int lane = threadIdx.x & 31;
    if (warp >= NN) return;
    const float* row = h + (size_t)warp * HH2;
    float acc[NC] = {0.f, 0.f, 0.f, 0.f, 0.f};
    for (int c = lane; c < HH2; c += 32) {
        float v = row[c];
#pragma unroll
        for (int j = 0; j < NC; j++) acc[j] += v * fcw[c * NC + j];
    }
#pragma unroll
    for (int j = 0; j < NC; j++)
#pragma unroll
        for (int o = 16; o; o >>= 1)
            acc[j] += __shfl_xor_sync(0xffffffffu, acc[j], o);
    if (lane == 0) {
        float mx = -1e30f;
#pragma unroll
        for (int j = 0; j < NC; j++) {
            acc[j] += fcb[j];
            mx = fmaxf(mx, acc[j]);
        }
        float s = 0.f;
#pragma unroll
        for (int j = 0; j < NC; j++) {
            acc[j] = expf(acc[j] - mx);
            s += acc[j];
        }
        float invs = 1.0f / s;
#pragma unroll
        for (int j = 0; j < NC; j++) out[(size_t)warp * NC + j] = acc[j] * invs;
    }
}

// ---------------------------------------------------------------------------
// Launch
// ---------------------------------------------------------------------------
static inline void run_gemm(const float* Aext, int Aid,
                            const float* B, const float* bias,
                            int Cid, int coff,
                            int M, int N, int K, int ldc,
                            bool relu, cudaStream_t st)
{
    dim3 grid(N / 128, (M + 127) / 128);
    if (relu) {
        if (bias) tgemm_kernel<true, true><<<grid, 256, 0, st>>>(Aext, Aid, B, bias, Cid, coff, M, N, K, ldc);
        else      tgemm_kernel<true, false><<<grid, 256, 0, st>>>(Aext, Aid, B, bias, Cid, coff, M, N, K, ldc);
    } else {
        if (bias) tgemm_kernel<false, true><<<grid, 256, 0, st>>>(Aext, Aid, B, bias, Cid, coff, M, N, K, ldc);
        else      tgemm_kernel<false, false><<<grid, 256, 0, st>>>(Aext, Aid, B, bias, Cid, coff, M, N, K, ldc);
    }
}

extern "C" void kernel_launch(void* const* d_in, const int* in_sizes, int n_in,
                              void* d_out, int out_size)
{
    const float* x        = (const float*)d_in[0];
    const int*   ei_raw   = (const int*)d_in[1];   // int32 or int64 — detected on device
    const float* W1       = (const float*)d_in[2];
    const float* att_src1 = (const float*)d_in[3];
    const float* att_dst1 = (const float*)d_in[4];
    const float* b_conv1  = (const float*)d_in[5];
    const float* A1       = (const float*)d_in[6];
    const float* b1       = (const float*)d_in[7];
    const float* W2       = (const float*)d_in[8];
    const float* att_src2 = (const float*)d_in[9];
    const float* att_dst2 = (const float*)d_in[10];
    const float* b_conv2  = (const float*)d_in[11];
    const float* A2       = (const float*)d_in[12];
    const float* b2       = (const float*)d_in[13];
    const float* Hw1      = (const float*)d_in[14];
    const float* Hb1      = (const float*)d_in[15];
    const float* Hw2      = (const float*)d_in[16];
    const float* Hb2      = (const float*)d_in[17];
    const float* Hw3      = (const float*)d_in[18];
    const float* Hb3      = (const float*)d_in[19];
    const float* fcw      = (const float*)d_in[20];
    const float* fcb      = (const float*)d_in[21];
    float*       out      = (float*)d_out;

    cudaStream_t st = 0;  // default stream (captured by harness)

    const int NB = (NN + 255) / 256;
    const int EB = (EE + 255) / 256;
    const int WB = (NN * 32 + 255) / 256;  // warp-per-node kernels

    // ---- Edge decode (dtype-agnostic) + CSR build (once per launch) ----
    detect_dtype_kernel<<<1, 1, 0, st>>>(ei_raw);
    convert_edges_kernel<<<EB, 256, 0, st>>>(ei_raw);
    init_csr_kernel<<<NB, 256, 0, st>>>();
    hist_kernel<<<EB, 256, 0, st>>>();
    scan_kernel<<<1, 1024, 0, st>>>();
    fill_kernel<<<EB, 256, 0, st>>>();

    // ---- Layer 1: hcat1 = [x@W1 | x@A1+b1] ----
    run_gemm(x, 0, W1, nullptr, BUF_HCAT1, 0,   NN, HH1, DIN, 1024, false, st);
    run_gemm(x, 0, A1, b1,      BUF_HCAT1, HH1, NN, HH1, DIN, 1024, false, st);
    att_dots_kernel<<<WB, 256, 0, st>>>(BUF_HCAT1, HH1, 1024, att_src1, att_dst1);
    init_ms_kernel<<<NB, 256, 0, st>>>();
    edge_max_kernel<<<EB, 256, 0, st>>>();
    edge_exp_kernel<<<EB, 256, 0, st>>>();
    aggregate_kernel<HH1, true><<<NN, HH1 / 4, 0, st>>>(
        BUF_HCAT1, 0, HH1, 1024, b_conv1, BUF_H1);

    // ---- Layer 2: hcat2 = [h1@W2 | h1@A2+b2] ----
    run_gemm(nullptr, BUF_H1, W2, nullptr, BUF_HCAT2, 0,   NN, HH2, HH1, 512, false, st);
    run_gemm(nullptr, BUF_H1, A2, b2,      BUF_HCAT2, HH2, NN, HH2, HH1, 512, false, st);
    att_dots_kernel<<<WB, 256, 0, st>>>(BUF_HCAT2, HH2, 512, att_src2, att_dst2);
    init_ms_kernel<<<NB, 256, 0, st>>>();
    edge_max_kernel<<<EB, 256, 0, st>>>();
    edge_exp_kernel<<<EB, 256, 0, st>>>();
    aggregate_kernel<HH2, false><<<NN, HH2 / 4, 0, st>>>(
        BUF_HCAT2, 0, HH2, 512, b_conv2, BUF_H2);

    // ---- MLP ----
    run_gemm(nullptr, BUF_H2,   Hw1, Hb1, BUF_MLP0, 0, NN, HH2, HH2, HH2, true, st);
    run_gemm(nullptr, BUF_MLP0, Hw2, Hb2, BUF_MLP1, 0, NN, HH2, HH2, HH2, true, st);
    run_gemm(nullptr, BUF_MLP1, Hw3, Hb3, BUF_MLP0, 0, NN, HH2, HH2, HH2, true, st);

    // ---- Classifier + softmax ----
    fc_softmax_kernel<<<WB, 256, 0, st>>>(BUF_MLP0, fcw, fcb, out);
}

// round 15
// speedup vs baseline: 2.7026x; 1.2706x over previous
#include <cuda_runtime.h>
#include <cuda_bf16.h>
#include <mma.h>
#include <math.h>

using namespace nvcuda;

// Problem constants
#define NN   50000
#define EE   800000
#define DIN  256
#define HH1  512
#define HH2  256
#define NC   5
#define NEG_SLOPE 0.2f

// ---------------------------------------------------------------------------
// Scratch (device globals; no allocation allowed). Resolved DEVICE-SIDE only.
// ---------------------------------------------------------------------------
__device__ float g_hcat1[(size_t)NN * 1024];  // [ x@W1 | x@A1+b1 ]   ld=1024
__device__ float g_hcat2[(size_t)NN * 512];   // [ h@W2 | h@A2+b2 ]   ld=512

// bf16 hi/lo activation planes (GEMM A operands / MLP outputs)
__device__ __nv_bfloat16 g_xhi [(size_t)NN * DIN], g_xlo [(size_t)NN * DIN];
__device__ __nv_bfloat16 g_h1hi[(size_t)NN * HH1], g_h1lo[(size_t)NN * HH1];
__device__ __nv_bfloat16 g_h2hi[(size_t)NN * HH2], g_h2lo[(size_t)NN * HH2];
__device__ __nv_bfloat16 g_m0hi[(size_t)NN * HH2], g_m0lo[(size_t)NN * HH2];
__device__ __nv_bfloat16 g_m1hi[(size_t)NN * HH2], g_m1lo[(size_t)NN * HH2];

// bf16 hi/lo weight planes (all 7 GEMM B operands, packed)
#define OFF_W1  0
#define OFF_A1  131072
#define OFF_W2  262144
#define OFF_A2  393216
#define OFF_HW1 524288
#define OFF_HW2 589824
#define OFF_HW3 655360
#define WTOT    720896
__device__ __nv_bfloat16 g_whi[WTOT], g_wlo[WTOT];

__device__ float g_as[NN], g_ad[NN];
__device__ float g_m[NN], g_s[NN];
__device__ float g_w[EE];

__device__ int g_src[EE];
__device__ int g_dst[EE];
__device__ int g_is64;

__device__ int g_deg[NN];
__device__ int g_rowoff[NN + 1];
__device__ int g_fill[NN];
__device__ int g_csrc[EE];
__device__ int g_ceid[EE];

// fp32 scratch ids
#define BUF_HCAT1 1
#define BUF_HCAT2 2
// activation-plane ids
#define AID_X  1
#define AID_H1 2
#define AID_H2 3
#define AID_M0 4
#define AID_M1 5

__device__ __forceinline__ float* scratch(int id)
{
    switch (id) {
        case BUF_HCAT1: return g_hcat1;
        case BUF_HCAT2: return g_hcat2;
        default:        return nullptr;
    }
}

__device__ __forceinline__ void act_planes(int id, __nv_bfloat16*& hi, __nv_bfloat16*& lo)
{
    switch (id) {
        case AID_X:  hi = g_xhi;  lo = g_xlo;  break;
        case AID_H1: hi = g_h1hi; lo = g_h1lo; break;
        case AID_H2: hi = g_h2hi; lo = g_h2lo; break;
        case AID_M0: hi = g_m0hi; lo = g_m0lo; break;
        case AID_M1: hi = g_m1hi; lo = g_m1lo; break;
        default:     hi = nullptr; lo = nullptr; break;
    }
}

// bf16 hi/lo split: hi = bf16(x), lo = bf16(x - hi)
__device__ __forceinline__ void split_bf16(float x, __nv_bfloat16& hi, __nv_bfloat16& lo)
{
    hi = __float2bfloat16(x);
    lo = __float2bfloat16(x - __bfloat162float(hi));
}

// ---------------------------------------------------------------------------
// cp.async helpers
// ---------------------------------------------------------------------------
__device__ __forceinline__ void cp16(void* smem, const void* gmem)
{
    unsigned s = (unsigned)__cvta_generic_to_shared(smem);
    asm volatile("cp.async.cg.shared.global [%0], [%1], 16;" :: "r"(s), "l"(gmem));
}
__device__ __forceinline__ void cp16z(void* smem, const void* gmem, int src_bytes)
{
    unsigned s = (unsigned)__cvta_generic_to_shared(smem);
    asm volatile("cp.async.cg.shared.global [%0], [%1], 16, %2;"
                 :: "r"(s), "l"(gmem), "r"(src_bytes));
}
#define CP_COMMIT() asm volatile("cp.async.commit_group;" ::: "memory")
#define CP_WAIT1()  asm volatile("cp.async.wait_group 1;" ::: "memory")

// ---------------------------------------------------------------------------
// One-time conversion kernels
// ---------------------------------------------------------------------------
__global__ void convert_w_kernel(const float* __restrict__ src, int off, int n)
{
    int i = blockIdx.x * blockDim.x + threadIdx.x;
    if (i < n) split_bf16(src[i], g_whi[off + i], g_wlo[off + i]);
}

__global__ void convert_x_kernel(const float* __restrict__ x)
{
    int i = blockIdx.x * blockDim.x + threadIdx.x;
    if (i < NN * DIN) split_bf16(x[i], g_xhi[i], g_xlo[i]);
}

// ---------------------------------------------------------------------------
// Edge-index dtype detection + conversion.
// ---------------------------------------------------------------------------
__global__ void detect_dtype_kernel(const int* __restrict__ raw)
{
    int all_zero = 1;
    for (int k = 0; k < 64; k++)
        if (raw[2 * k + 1] != 0) { all_zero = 0; break; }
    g_is64 = all_zero;
}

__global__ void convert_edges_kernel(const int* __restrict__ raw)
{
    int e = blockIdx.x * blockDim.x + threadIdx.x;
    if (e >= EE) return;
    if (g_is64) {
        g_src[e] = raw[2 * e];
        g_dst[e] = raw[2 * (EE + e)];
    } else {
        g_src[e] = raw[e];
        g_dst[e] = raw[EE + e];
    }
}

// ---------------------------------------------------------------------------
// Tensor-core GEMM (3x bf16 split, cp.async double-buffered).
// C[M,N] = A[M,K] @ B[K,N] (+bias)(+relu).
// A from bf16 hi/lo activation planes; B from weight planes at boff.
// BM=BN=128, BK=16, 2-stage pipeline. 8 warps (2x4), warp tile 64x32.
// Output: fp32 scratch (Cid,coff,ldc) or bf16 hi/lo planes (outid), OUTBF.
// ---------------------------------------------------------------------------
struct Stage {
    __nv_bfloat16 Ahi[128][24];   // ld=24 halves (48B rows, 16B-aligned)
    __nv_bfloat16 Alo[128][24];
    __nv_bfloat16 Bhi[16][136];   // ld=136 halves (272B rows, 16B-aligned)
    __nv_bfloat16 Blo[16][136];
};

__device__ __forceinline__ void issue_stage(
    Stage& st,
    const __nv_bfloat16* __restrict__ Ahi, const __nv_bfloat16* __restrict__ Alo,
    const __nv_bfloat16* __restrict__ Bhi, const __nv_bfloat16* __restrict__ Blo,
    int row0, int col0, int k0, int M, int N, int K, int tid)
{
#pragma unroll
    for (int i = 0; i < 4; i++) {
        int chunk = tid + i * 256;           // 0..1023
        if (chunk < 512) {                   // A planes: 2 x 128 rows x 2 chunks
            int plane = chunk >> 8;
            int idx = chunk & 255;
            int r = idx >> 1;
            int h8 = (idx & 1) * 8;          // halves
            const __nv_bfloat16* g = (plane ? Alo : Ahi) + (size_t)(row0 + r) * K + k0 + h8;
            __nv_bfloat16* s = (plane ? st.Alo[r] : st.Ahi[r]) + h8;
            cp16z(s, g, (row0 + r < M) ? 16 : 0);
        } else {                             // B planes: 2 x 16 rows x 16 chunks
            int c2 = chunk - 512;
            int plane = c2 >> 8;
            int idx = c2 & 255;
            int r = idx >> 4;
            int h8 = (idx & 15) * 8;
            const __nv_bfloat16* g = (plane ? Blo : Bhi) + (size_t)(k0 + r) * N + col0 + h8;
            __nv_bfloat16* s = (plane ? st.Blo[r] : st.Bhi[r]) + h8;
            cp16(s, g);
        }
    }
}

template <bool RELU, bool BIAS, bool OUTBF>
__global__ __launch_bounds__(256) void tgemm_kernel(
    int Aid, int boff, const float* __restrict__ bias,
    int outid, int coff, int M, int N, int K, int ldc)
{
    __nv_bfloat16 *Ahi, *Alo;
    act_planes(Aid, Ahi, Alo);
    const __nv_bfloat16* Bhi = g_whi + boff;
    const __nv_bfloat16* Blo = g_wlo + boff;

    __shared__ union {
        Stage st[2];
        float Cst[128][68];
    } sm;

    int tid = threadIdx.x;
    int warp = tid >> 5;
    int wr = warp >> 2;          // 0..1 -> 64 rows each
    int wc = warp & 3;           // 0..3 -> 32 cols each
    int row0 = blockIdx.y * 128;
    int col0 = blockIdx.x * 128;

    wmma::fragment<wmma::accumulator, 16, 16, 16, float> acc[4][2];
#pragma unroll
    for (int mt = 0; mt < 4; mt++)
#pragma unroll
        for (int nt = 0; nt < 2; nt++) wmma::fill_fragment(acc[mt][nt], 0.f);

    int ntiles = K / 16;
    issue_stage(sm.st[0], Ahi, Alo, Bhi, Blo, row0, col0, 0, M, N, K, tid);
    CP_COMMIT();

    for (int t = 0; t < ntiles; t++) {
        if (t + 1 < ntiles)
            issue_stage(sm.st[(t + 1) & 1], Ahi, Alo, Bhi, Blo,
                        row0, col0, (t + 1) * 16, M, N, K, tid);
        CP_COMMIT();
        CP_WAIT1();
        __syncthreads();

        Stage& st = sm.st[t & 1];
        wmma::fragment<wmma::matrix_b, 16, 16, 16, __nv_bfloat16, wmma::row_major> fbhi[2], fblo[2];
#pragma unroll
        for (int nt = 0; nt < 2; nt++) {
            int c = wc * 32 + nt * 16;
            wmma::load_matrix_sync(fbhi[nt], &st.Bhi[0][c], 136);
            wmma::load_matrix_sync(fblo[nt], &st.Blo[0][c], 136);
        }
#pragma unroll
        for (int mt = 0; mt < 4; mt++) {
            int r = wr * 64 + mt * 16;
            wmma::fragment<wmma::matrix_a, 16, 16, 16, __nv_bfloat16, wmma::row_major> fahi, falo;
            wmma::load_matrix_sync(fahi, &st.Ahi[r][0], 24);
            wmma::load_matrix_sync(falo, &st.Alo[r][0], 24);
#pragma unroll
            for (int nt = 0; nt < 2; nt++) {
                wmma::mma_sync(acc[mt][nt], fahi, fbhi[nt], acc[mt][nt]);
                wmma::mma_sync(acc[mt][nt], fahi, fblo[nt], acc[mt][nt]);
                wmma::mma_sync(acc[mt][nt], falo, fbhi[nt], acc[mt][nt]);
            }
        }
        __syncthreads();
    }

    // Epilogue: two 64-column halves through shared staging
    __nv_bfloat16 *Chi = nullptr, *Clo = nullptr;
    float* C = nullptr;
    if (OUTBF) act_planes(outid, Chi, Clo);
    else       C = scratch(outid) + coff;

#pragma unroll
    for (int half = 0; half < 2; half++) {
        if ((wc >> 1) == half) {
            int wcl = wc & 1;
#pragma unroll
            for (int mt = 0; mt < 4; mt++)
#pragma unroll
                for (int nt = 0; nt < 2; nt++)
                    wmma::store_matrix_sync(&sm.Cst[wr * 64 + mt * 16][wcl * 32 + nt * 16],
                                            acc[mt][nt], 68, wmma::mem_row_major);
        }
        __syncthreads();
#pragma unroll
        for (int i = 0; i < 8; i++) {
            int idx = tid + i * 256;
            int r = idx >> 4;            // 0..127
            int c = (idx & 15) * 4;      // 0..60
            if (row0 + r < M) {
                int gc = col0 + half * 64 + c;
                float4 v = *(const float4*)(&sm.Cst[r][c]);
                if (BIAS) {
                    v.x += bias[gc];
                    v.y += bias[gc + 1];
                    v.z += bias[gc + 2];
                    v.w += bias[gc + 3];
                }
                if (RELU) {
                    v.x = fmaxf(v.x, 0.f);
                    v.y = fmaxf(v.y, 0.f);
                    v.z = fmaxf(v.z, 0.f);
                    v.w = fmaxf(v.w, 0.f);
                }
                if (OUTBF) {
                    size_t base = (size_t)(row0 + r) * N + gc;
                    __nv_bfloat16 h0, l0, h1, l1, h2, l2, h3, l3;
                    split_bf16(v.x, h0, l0);
                    split_bf16(v.y, h1, l1);
                    split_bf16(v.z, h2, l2);
                    split_bf16(v.w, h3, l3);
                    *(__nv_bfloat162*)(Chi + base)     = __nv_bfloat162(h0, h1);
                    *(__nv_bfloat162*)(Chi + base + 2) = __nv_bfloat162(h2, h3);
                    *(__nv_bfloat162*)(Clo + base)     = __nv_bfloat162(l0, l1);
                    *(__nv_bfloat162*)(Clo + base + 2) = __nv_bfloat162(l2, l3);
                } else {
                    *(float4*)(C + (size_t)(row0 + r) * ldc + gc) = v;
                }
            }
        }
        __syncthreads();
    }
}

// ---------------------------------------------------------------------------
// Attention dot products: warp per node (fp32 hcat input).
// ---------------------------------------------------------------------------
__global__ void att_dots_kernel(int hid, int C, int ld,
                                const float* __restrict__ asv,
                                const float* __restrict__ adv)
{
    const float* h = scratch(hid);
    int warp = (blockIdx.x * blockDim.x + threadIdx.x) >> 5;
    int lane = threadIdx.x & 31;
    if (warp >= NN) return;
    const float* row = h + (size_t)warp * ld;
    float s1 = 0.f, s2 = 0.f;
    for (int c = lane; c < C; c += 32) {
        float v = row[c];
        s1 += v * asv[c];
        s2 += v * adv[c];
    }
#pragma unroll
    for (int o = 16; o; o >>= 1) {
        s1 += __shfl_xor_sync(0xffffffffu, s1, o);
        s2 += __shfl_xor_sync(0xffffffffu, s2, o);
    }
    if (lane == 0) { g_as[warp] = s1; g_ad[warp] = s2; }
}

// ---------------------------------------------------------------------------
// CSR build
// ---------------------------------------------------------------------------
__global__ void init_csr_kernel()
{
    int i = blockIdx.x * blockDim.x + threadIdx.x;
    if (i < NN) { g_deg[i] = 0; g_fill[i] = 0; }
}

__global__ void init_ms_kernel()
{
    int i = blockIdx.x * blockDim.x + threadIdx.x;
    if (i < NN) { g_m[i] = -1e30f; g_s[i] = 0.f; }
}

__global__ void hist_kernel()
{
    int e = blockIdx.x * blockDim.x + threadIdx.x;
    if (e < EE) atomicAdd(&g_deg[g_dst[e]], 1);
}

__global__ __launch_bounds__(1024) void scan_kernel()
{
    __shared__ int wsum[32];
    __shared__ int running;
    int tid = threadIdx.x;
    int lane = tid & 31, wid = tid >> 5;
    if (tid == 0) running = 0;
    __syncthreads();
    for (int base = 0; base < NN; base += 1024) {
        int i = base + tid;
        int v = (i < NN) ? g_deg[i] : 0;
        int x = v;
#pragma unroll
        for (int o = 1; o < 32; o <<= 1) {
            int y = __shfl_up_sync(0xffffffffu, x, o);
            if (lane >= o) x += y;
        }
        if (lane == 31) wsum[wid] = x;
        __syncthreads();
        if (wid == 0) {
            int w = wsum[lane];
#pragma unroll
            for (int o = 1; o < 32; o <<= 1) {
                int y = __shfl_up_sync(0xffffffffu, w, o);
                if (lane >= o) w += y;
            }
            wsum[lane] = w;
        }
        __syncthreads();
        int excl = x - v + (wid > 0 ? wsum[wid - 1] : 0);
        if (i < NN) g_rowoff[i] = running + excl;
        int total = wsum[31];
        __syncthreads();
        if (tid == 0) running += total;
        __syncthreads();
    }
    if (tid == 0) g_rowoff[NN] = running;
}

__global__ void fill_kernel()
{
    int e = blockIdx.x * blockDim.x + threadIdx.x;
    if (e < EE) {
        int d = g_dst[e];
        int p = g_rowoff[d] + atomicAdd(&g_fill[d], 1);
        g_csrc[p] = g_src[e];
        g_ceid[p] = e;
    }
}

// ---------------------------------------------------------------------------
// Edge softmax
// ---------------------------------------------------------------------------
__device__ __forceinline__ void atomicMaxF(float* addr, float val)
{
    int old = __float_as_int(*addr);
    while (__int_as_float(old) < val) {
        int assumed = old;
        old = atomicCAS((int*)addr, assumed, __float_as_int(val));
        if (old == assumed) break;
    }
}

__global__ void edge_max_kernel()
{
    int e = blockIdx.x * blockDim.x + threadIdx.x;
    if (e >= EE) return;
    float t = g_as[g_src[e]] + g_ad[g_dst[e]];
    t = (t > 0.f) ? t : NEG_SLOPE * t;   // leaky relu
    g_w[e] = t;
    atomicMaxF(&g_m[g_dst[e]], t);
}

__global__ void edge_exp_kernel()
{
    int e = blockIdx.x * blockDim.x + threadIdx.x;
    if (e >= EE) return;
    int d = g_dst[e];
    float w = expf(g_w[e] - g_m[d]);
    g_w[e] = w;
    atomicAdd(&g_s[d], w);
}

// ---------------------------------------------------------------------------
// Aggregation: block per dst node, C/4 threads, one float4 per thread.
// Reads fp32 hcat (h part + residual); writes bf16 hi/lo planes (oid).
// ---------------------------------------------------------------------------
template <int C, bool RELU>
__global__ void aggregate_kernel(int hid, int hoff, int roff, int ldh,
                                 const float* __restrict__ bias, int oid)
{
    const float* base = scratch(hid);
    const float* h = base + hoff;
    const float* res = base + roff;
    __nv_bfloat16 *ohi, *olo;
    act_planes(oid, ohi, olo);

    int n = blockIdx.x;
    int t4 = threadIdx.x * 4;
    int beg = g_rowoff[n], end = g_rowoff[n + 1];
    float inv = 1.0f / (g_s[n] + 1e-16f);
    float4 acc = make_float4(0.f, 0.f, 0.f, 0.f);
    int j = beg;
    for (; j + 1 < end; j += 2) {
        int s0 = g_csrc[j], s1 = g_csrc[j + 1];
        float c0 = g_w[g_ceid[j]] * inv;
        float c1 = g_w[g_ceid[j + 1]] * inv;
        float4 h0 = *(const float4*)(h + (size_t)s0 * ldh + t4);
        float4 h1 = *(const float4*)(h + (size_t)s1 * ldh + t4);
        acc.x += c0 * h0.x + c1 * h1.x;
        acc.y += c0 * h0.y + c1 * h1.y;
        acc.z += c0 * h0.z + c1 * h1.z;
        acc.w += c0 * h0.w + c1 * h1.w;
    }
    if (j < end) {
        int s0 = g_csrc[j];
        float c0 = g_w[g_ceid[j]] * inv;
        float4 h0 = *(const float4*)(h + (size_t)s0 * ldh + t4);
        acc.x += c0 * h0.x;
        acc.y += c0 * h0.y;
        acc.z += c0 * h0.z;
        acc.w += c0 * h0.w;
    }
    float4 r = *(const float4*)(res + (size_t)n * ldh + t4);
    float4 o;
    o.x = acc.x + r.x + bias[t4 + 0];
    o.y = acc.y + r.y + bias[t4 + 1];
    o.z = acc.z + r.z + bias[t4 + 2];
    o.w = acc.w + r.w + bias[t4 + 3];
    if (RELU) {
        o.x = fmaxf(o.x, 0.f);
        o.y = fmaxf(o.y, 0.f);
        o.z = fmaxf(o.z, 0.f);
        o.w = fmaxf(o.w, 0.f);
    }
    __nv_bfloat16 h0, l0, h1, l1, h2, l2, h3, l3;
    split_bf16(o.x, h0, l0);
    split_bf16(o.y, h1, l1);
    split_bf16(o.z, h2, l2);
    split_bf16(o.w, h3, l3);
    size_t ob = (size_t)n * C + t4;
    *(__nv_bfloat162*)(ohi + ob)     = __nv_bfloat162(h0, h1);
    *(__nv_bfloat162*)(ohi + ob + 2) = __nv_bfloat162(h2, h3);
    *(__nv_bfloat162*)(olo + ob)     = __nv_bfloat162(l0, l1);
    *(__nv_bfloat162*)(olo + ob + 2) = __nv_bfloat162(l2, l3);
}

// ---------------------------------------------------------------------------
// Classifier + softmax: warp per node (reads bf16 hi/lo planes).
// ---------------------------------------------------------------------------
__global__ void fc_softmax_kernel(int hid,
                                  const float* __restrict__ fcw,
                                  const float* __restrict__ fcb,
                                  float* __restrict__ out)
{
    __nv_bfloat16 *hhi, *hlo;
    act_planes(hid, hhi, hlo);
    int warp = (blockIdx.x * blockDim.x + threadIdx.x) >> 5;
    int lane = threadIdx.x & 31;
    if (warp >= NN) return;
    size_t rb = (size_t)warp * HH2;
    float acc[NC] = {0.f, 0.f, 0.f, 0.f, 0.f};
    for (int c = lane; c < HH2; c += 32) {
        float v = __bfloat162float(hhi[rb + c]) + __bfloat162float(hlo[rb + c]);
#pragma unroll
        for (int j = 0; j < NC; j++) acc[j] += v * fcw[c * NC + j];
    }
#pragma unroll
    for (int j = 0; j < NC; j++)
#pragma unroll
        for (int o = 16; o; o >>= 1)
            acc[j] += __shfl_xor_sync(0xffffffffu, acc[j], o);
    if (lane == 0) {
        float mx = -1e30f;
#pragma unroll
        for (int j = 0; j < NC; j++) {
            acc[j] += fcb[j];
            mx = fmaxf(mx, acc[j]);
        }
        float s = 0.f;
#pragma unroll
        for (int j = 0; j < NC; j++) {
            acc[j] = expf(acc[j] - mx);
            s += acc[j];
        }
        float invs = 1.0f / s;
#pragma unroll
        for (int j = 0; j < NC; j++) out[(size_t)warp * NC + j] = acc[j] * invs;
    }
}

// ---------------------------------------------------------------------------
// Launch
// ---------------------------------------------------------------------------
extern "C" void kernel_launch(void* const* d_in, const int* in_sizes, int n_in,
                              void* d_out, int out_size)
{
    const float* x        = (const float*)d_in[0];
    const int*   ei_raw   = (const int*)d_in[1];   // int32 or int64 — detected on device
    const float* W1       = (const float*)d_in[2];
    const float* att_src1 = (const float*)d_in[3];
    const float* att_dst1 = (const float*)d_in[4];
    const float* b_conv1  = (const float*)d_in[5];
    const float* A1       = (const float*)d_in[6];
    const float* b1       = (const float*)d_in[7];
    const float* W2       = (const float*)d_in[8];
    const float* att_src2 = (const float*)d_in[9];
    const float* att_dst2 = (const float*)d_in[10];
    const float* b_conv2  = (const float*)d_in[11];
    const float* A2       = (const float*)d_in[12];
    const float* b2       = (const float*)d_in[13];
    const float* Hw1      = (const float*)d_in[14];
    const float* Hb1      = (const float*)d_in[15];
    const float* Hw2      = (const float*)d_in[16];
    const float* Hb2      = (const float*)d_in[17];
    const float* Hw3      = (const float*)d_in[18];
    const float* Hb3      = (const float*)d_in[19];
    const float* fcw      = (const float*)d_in[20];
    const float* fcb      = (const float*)d_in[21];
    float*       out      = (float*)d_out;

    cudaStream_t st = 0;

    const int NB = (NN + 255) / 256;
    const int EB = (EE + 255) / 256;
    const int WB = (NN * 32 + 255) / 256;

    // ---- Edge decode + CSR build ----
    detect_dtype_kernel<<<1, 1, 0, st>>>(ei_raw);
    convert_edges_kernel<<<EB, 256, 0, st>>>(ei_raw);
    init_csr_kernel<<<NB, 256, 0, st>>>();
    hist_kernel<<<EB, 256, 0, st>>>();
    scan_kernel<<<1, 1024, 0, st>>>();
    fill_kernel<<<EB, 256, 0, st>>>();

    // ---- One-time bf16 hi/lo conversions (weights + x) ----
    convert_w_kernel<<<512, 256, 0, st>>>(W1,  OFF_W1,  DIN * HH1);
    convert_w_kernel<<<512, 256, 0, st>>>(A1,  OFF_A1,  DIN * HH1);
    convert_w_kernel<<<512, 256, 0, st>>>(W2,  OFF_W2,  HH1 * HH2);
    convert_w_kernel<<<512, 256, 0, st>>>(A2,  OFF_A2,  HH1 * HH2);
    convert_w_kernel<<<256, 256, 0, st>>>(Hw1, OFF_HW1, HH2 * HH2);
    convert_w_kernel<<<256, 256, 0, st>>>(Hw2, OFF_HW2, HH2 * HH2);
    convert_w_kernel<<<256, 256, 0, st>>>(Hw3, OFF_HW3, HH2 * HH2);
    convert_x_kernel<<<(NN * DIN + 255) / 256, 256, 0, st>>>(x);

    dim3 g4(4, (NN + 127) / 128);   // N=512
    dim3 g2(2, (NN + 127) / 128);   // N=256

    // ---- Layer 1: hcat1 = [x@W1 | x@A1+b1] (fp32) ----
    tgemm_kernel<false, false, false><<<g4, 256, 0, st>>>(AID_X, OFF_W1, nullptr, BUF_HCAT1, 0,   NN, HH1, DIN, 1024);
    tgemm_kernel<false, true,  false><<<g4, 256, 0, st>>>(AID_X, OFF_A1, b1,      BUF_HCAT1, HH1, NN, HH1, DIN, 1024);
    att_dots_kernel<<<WB, 256, 0, st>>>(BUF_HCAT1, HH1, 1024, att_src1, att_dst1);
    init_ms_kernel<<<NB, 256, 0, st>>>();
    edge_max_kernel<<<EB, 256, 0, st>>>();
    edge_exp_kernel<<<EB, 256, 0, st>>>();
    aggregate_kernel<HH1, true><<<NN, HH1 / 4, 0, st>>>(
        BUF_HCAT1, 0, HH1, 1024, b_conv1, AID_H1);

    // ---- Layer 2: hcat2 = [h1@W2 | h1@A2+b2] (fp32) ----
    tgemm_kernel<false, false, false><<<g2, 256, 0, st>>>(AID_H1, OFF_W2, nullptr, BUF_HCAT2, 0,   NN, HH2, HH1, 512);
    tgemm_kernel<false, true,  false><<<g2, 256, 0, st>>>(AID_H1, OFF_A2, b2,      BUF_HCAT2, HH2, NN, HH2, HH1, 512);
    att_dots_kernel<<<WB, 256, 0, st>>>(BUF_HCAT2, HH2, 512, att_src2, att_dst2);
    init_ms_kernel<<<NB, 256, 0, st>>>();
    edge_max_kernel<<<EB, 256, 0, st>>>();
    edge_exp_kernel<<<EB, 256, 0, st>>>();
    aggregate_kernel<HH2, false><<<NN, HH2 / 4, 0, st>>>(
        BUF_HCAT2, 0, HH2, 512, b_conv2, AID_H2);

    // ---- MLP (bf16 plane outputs) ----
    tgemm_kernel<true, true, true><<<g2, 256, 0, st>>>(AID_H2, OFF_HW1, Hb1, AID_M0, 0, NN, HH2, HH2, HH2);
    tgemm_kernel<true, true, true><<<g2, 256, 0, st>>>(AID_M0, OFF_HW2, Hb2, AID_M1, 0, NN, HH2, HH2, HH2);
    tgemm_kernel<true, true, true><<<g2, 256, 0, st>>>(AID_M1, OFF_HW3, Hb3, AID_M0, 0, NN, HH2, HH2, HH2);

    // ---- Classifier + softmax ----
    fc_softmax_kernel<<<WB, 256, 0, st>>>(AID_M0, fcw, fcb, out);
}